// round 9
// baseline (speedup 1.0000x reference)
#include <cuda_runtime.h>
#include <cuda_bf16.h>
#include <cstdint>

#define N_NODES 50000
#define D 96
#define D4 (D / 4)            // 24 float4 per row
#define SLOTS 128             // max neighbors per node (avg deg 16)
#define BM 64                 // rows per MLP tile
#define PW 100                // Wp row stride (uint2)
#define PX 52                 // Xp row stride (uint2); rows 16B-aligned
#define NK2 (D / 2)           // 48 packed-k rows
#define NTILES ((N_NODES + BM - 1) / BM)   // 782
#define MLP_BLOCKS 296

// Scratch (device globals: no allocation allowed)
__device__ int g_cnt[N_NODES];
__device__ int g_slots[(size_t)N_NODES * SLOTS];
__device__ __align__(16) uint2 g_rstp[(size_t)N_NODES * NK2]; // packed bf16 hi/lo
__device__ __align__(16) uint2 g_w1p[NK2 * D];   // (hi bf16x2, lo bf16x2), [k2][n]
__device__ __align__(16) uint2 g_w2p[NK2 * D];

// ---------------------------------------------------------------------------
// helpers
// ---------------------------------------------------------------------------
__device__ __forceinline__ void mma16(float c[4],
                                      uint32_t a0, uint32_t a1, uint32_t a2, uint32_t a3,
                                      uint32_t b0, uint32_t b1) {
    asm volatile(
        "mma.sync.aligned.m16n8k16.row.col.f32.bf16.bf16.f32 "
        "{%0,%1,%2,%3}, {%4,%5,%6,%7}, {%8,%9}, {%0,%1,%2,%3};"
        : "+f"(c[0]), "+f"(c[1]), "+f"(c[2]), "+f"(c[3])
        : "r"(a0), "r"(a1), "r"(a2), "r"(a3), "r"(b0), "r"(b1));
}

// Split (x0, x1) into packed bf16x2 hi + lo residual
__device__ __forceinline__ uint2 split_bf16x2(float x0, float x1) {
    __nv_bfloat162 hi = __floats2bfloat162_rn(x0, x1);
    float r0 = x0 - __bfloat162float(hi.x);
    float r1 = x1 - __bfloat162float(hi.y);
    __nv_bfloat162 lo = __floats2bfloat162_rn(r0, r1);
    uint2 v;
    v.x = *reinterpret_cast<uint32_t*>(&hi);
    v.y = *reinterpret_cast<uint32_t*>(&lo);
    return v;
}

// ---------------------------------------------------------------------------
// Step 0: zero counters + build packed bf16 hi/lo weights [k2][n]
// ---------------------------------------------------------------------------
__global__ void prep_kernel(const float* __restrict__ W1,
                            const float* __restrict__ W2) {
    int i = blockIdx.x * blockDim.x + threadIdx.x;
    if (i < N_NODES) g_cnt[i] = 0;
    if (i < NK2 * D) {
        int k2 = i / D, n = i % D;
        float a0 = W1[(2 * k2) * D + n];
        float a1 = W1[(2 * k2 + 1) * D + n];
        g_w1p[i] = split_bf16x2(a0, a1);
        a0 = W2[(2 * k2) * D + n];
        a1 = W2[(2 * k2 + 1) * D + n];
        g_w2p[i] = split_bf16x2(a0, a1);
    }
}

// ---------------------------------------------------------------------------
// Step 1: bucket edge sources into per-destination slot table, 4 edges/thread
// ---------------------------------------------------------------------------
__global__ void fill_slots(const int* __restrict__ src,
                           const int* __restrict__ dst, int n_edges) {
    int t = blockIdx.x * blockDim.x + threadIdx.x;
    int e0 = t * 4;
    if (e0 + 3 < n_edges) {
        int4 s4 = *reinterpret_cast<const int4*>(src + e0);
        int4 d4 = *reinterpret_cast<const int4*>(dst + e0);
        int p0 = atomicAdd(&g_cnt[d4.x], 1);
        int p1 = atomicAdd(&g_cnt[d4.y], 1);
        int p2 = atomicAdd(&g_cnt[d4.z], 1);
        int p3 = atomicAdd(&g_cnt[d4.w], 1);
        if (p0 < SLOTS) g_slots[(size_t)d4.x * SLOTS + p0] = s4.x;
        if (p1 < SLOTS) g_slots[(size_t)d4.y * SLOTS + p1] = s4.y;
        if (p2 < SLOTS) g_slots[(size_t)d4.z * SLOTS + p2] = s4.z;
        if (p3 < SLOTS) g_slots[(size_t)d4.w * SLOTS + p3] = s4.w;
    } else {
        for (int e = e0; e < n_edges; e++) {
            int d = dst[e];
            int pos = atomicAdd(&g_cnt[d], 1);
            if (pos < SLOTS) g_slots[(size_t)d * SLOTS + pos] = src[e];
        }
    }
}

// ---------------------------------------------------------------------------
// Step 2: gather  rstp[n] = pack_bf16(feat[n] + sum_{s in slots[n]} feat[s])
// 4 nodes per warp, 8 lanes per node, 3 float4 chunks per lane. (proven R6-R8)
// ---------------------------------------------------------------------------
__global__ void __launch_bounds__(256)
gather_kernel(const float4* __restrict__ featv) {
    const int lane = threadIdx.x & 31;
    const int warp = threadIdx.x >> 5;
    const int g    = lane >> 3;       // group 0..3
    const int sl   = lane & 7;        // sublane 0..7
    const int n = (blockIdx.x * 8 + warp) * 4 + g;
    if (blockIdx.x * 32 + warp * 4 >= N_NODES) return;

    const bool valid = (n < N_NODES);
    int cnt = valid ? g_cnt[n] : 0;
    if (cnt > SLOTS) cnt = SLOTS;
    const int* slp = g_slots + (size_t)n * SLOTS;

    float4 a0 = make_float4(0.f, 0.f, 0.f, 0.f);
    float4 a1 = a0, a2 = a0;
    if (valid) {
        const float4* row = featv + (size_t)n * D4;
        a0 = __ldg(row + sl);
        a1 = __ldg(row + sl + 8);
        a2 = __ldg(row + sl + 16);
    }

    int mc = cnt;
    #pragma unroll
    for (int o = 16; o >= 4; o >>= 1)
        mc = max(mc, __shfl_xor_sync(0xffffffffu, mc, o));

    for (int base = 0; base < mc; base += 8) {
        int idx = (base + sl < cnt) ? __ldg(slp + base + sl) : -1;
        #pragma unroll
        for (int k = 0; k < 8; k++) {
            int s = __shfl_sync(0xffffffffu, idx, (g << 3) + k);
            if (s >= 0) {
                const float4* row = featv + (size_t)s * D4;
                float4 v0 = __ldg(row + sl);
                float4 v1 = __ldg(row + sl + 8);
                float4 v2 = __ldg(row + sl + 16);
                a0.x += v0.x; a0.y += v0.y; a0.z += v0.z; a0.w += v0.w;
                a1.x += v1.x; a1.y += v1.y; a1.z += v1.z; a1.w += v1.w;
                a2.x += v2.x; a2.y += v2.y; a2.z += v2.z; a2.w += v2.w;
            }
        }
    }

    if (valid) {
        uint4* out = reinterpret_cast<uint4*>(g_rstp + (size_t)n * NK2);
        uint2 p;
        uint4 q;
        p = split_bf16x2(a0.x, a0.y); q.x = p.x; q.y = p.y;
        p = split_bf16x2(a0.z, a0.w); q.z = p.x; q.w = p.y;
        out[sl] = q;
        p = split_bf16x2(a1.x, a1.y); q.x = p.x; q.y = p.y;
        p = split_bf16x2(a1.z, a1.w); q.z = p.x; q.w = p.y;
        out[sl + 8] = q;
        p = split_bf16x2(a2.x, a2.y); q.x = p.x; q.y = p.y;
        p = split_bf16x2(a2.z, a2.w); q.z = p.x; q.w = p.y;
        out[sl + 16] = q;
    }
}

// ---------------------------------------------------------------------------
// Step 3: tensor-core MLP via 3xBF16. Persistent blocks stage W1+W2 once,
// loop over 64-row tiles. Warp tile = M32 x N24: 2 row groups x 4 column
// quarters. Per kk: 8 A-LDS + 6 B-LDS feed 36 MMAs (loads/MMA = 0.39).
// B-fragment banks (8*tq + 2*qid) are all-distinct: conflict-free.
// ---------------------------------------------------------------------------
__global__ void __launch_bounds__(256, 2)
mlp_mma(const float* __restrict__ b1, const float* __restrict__ b2,
        float* __restrict__ Y, int nrows) {
    extern __shared__ uint2 smem_u2[];
    uint2* W1s = smem_u2;                // NK2 * PW = 4800 uint2
    uint2* W2s = smem_u2 + NK2 * PW;     // 4800 uint2
    uint2* Xp  = smem_u2 + 2 * NK2 * PW; // BM * PX = 3328 uint2

    const int tid  = threadIdx.x;
    const int lane = tid & 31;
    const int warp = tid >> 5;        // 0..7
    const int rg   = warp >> 2;       // row group 0..1 (32 rows each)
    const int ch   = (warp & 3) * 24; // column quarter base
    const int qid  = lane >> 2;       // 0..7
    const int tq   = lane & 3;        // 0..3

    // Stage both weight matrices once per block
    for (int i = tid; i < NK2 * D; i += 256) {
        int k2 = i / D, n = i % D;
        W1s[k2 * PW + n] = g_w1p[i];
        W2s[k2 * PW + n] = g_w2p[i];
    }

    const int rbase = rg * 32;
    const int r0 = rbase + qid;       // rows r0, r0+8 (rb=0); r0+16, r0+24 (rb=1)
    const float2* b1v = reinterpret_cast<const float2*>(b1);
    const float2* b2v = reinterpret_cast<const float2*>(b2);

    for (int t = blockIdx.x; t < NTILES; t += MLP_BLOCKS) {
        const int row0 = t * BM;

        // Stage X tile: pure vector copy (packed in gather)
        {
            const uint4* srcv = reinterpret_cast<const uint4*>(
                g_rstp + (size_t)row0 * NK2);
            int limit = min(BM, nrows - row0) * (NK2 / 2);  // uint4 count
            #pragma unroll
            for (int i = tid; i < BM * (NK2 / 2); i += 256) {
                int r = i / (NK2 / 2), j = i % (NK2 / 2);
                uint4 v = make_uint4(0u, 0u, 0u, 0u);
                if (i < limit) v = __ldg(srcv + i);
                reinterpret_cast<uint4*>(Xp + r * PX)[j] = v;
            }
        }
        __syncthreads();

        float c[2][3][4];

        // ---- Phase 1: H = relu(X @ W1 + b1) ----
        #pragma unroll
        for (int rb = 0; rb < 2; rb++)
            #pragma unroll
            for (int nn = 0; nn < 3; nn++)
                #pragma unroll
                for (int j = 0; j < 4; j++) c[rb][nn][j] = 0.f;

        #pragma unroll
        for (int kk = 0; kk < 6; kk++) {
            const int kb = kk * 8 + tq;
            uint2 A[2][4];
            #pragma unroll
            for (int rb = 0; rb < 2; rb++) {
                int rr = r0 + rb * 16;
                A[rb][0] = Xp[rr * PX + kb];
                A[rb][1] = Xp[(rr + 8) * PX + kb];
                A[rb][2] = Xp[rr * PX + kb + 4];
                A[rb][3] = Xp[(rr + 8) * PX + kb + 4];
            }
            #pragma unroll
            for (int nn = 0; nn < 3; nn++) {
                uint2 B0 = W1s[kb * PW + ch + nn * 8 + qid];
                uint2 B1 = W1s[(kb + 4) * PW + ch + nn * 8 + qid];
                #pragma unroll
                for (int rb = 0; rb < 2; rb++) {
                    mma16(c[rb][nn], A[rb][0].x, A[rb][1].x, A[rb][2].x, A[rb][3].x, B0.x, B1.x);
                    mma16(c[rb][nn], A[rb][0].x, A[rb][1].x, A[rb][2].x, A[rb][3].x, B0.y, B1.y);
                    mma16(c[rb][nn], A[rb][0].y, A[rb][1].y, A[rb][2].y, A[rb][3].y, B0.x, B1.x);
                }
            }
        }

        __syncthreads();   // phase-1 reads of Xp complete

        // Write H (relu, re-split) back into Xp
        #pragma unroll
        for (int rb = 0; rb < 2; rb++) {
            #pragma unroll
            for (int nn = 0; nn < 3; nn++) {
                int col = ch + nn * 8 + 2 * tq;
                float2 bb = __ldg(b1v + (col >> 1));
                float h00 = fmaxf(c[rb][nn][0] + bb.x, 0.f);
                float h01 = fmaxf(c[rb][nn][1] + bb.y, 0.f);
                float h10 = fmaxf(c[rb][nn][2] + bb.x, 0.f);
                float h11 = fmaxf(c[rb][nn][3] + bb.y, 0.f);
                int k2 = col >> 1;
                int ra = r0 + rb * 16;
                Xp[ra * PX + k2]       = split_bf16x2(h00, h01);
                Xp[(ra + 8) * PX + k2] = split_bf16x2(h10, h11);
            }
        }
        __syncthreads();

        // ---- Phase 2: Y = H @ W2 + b2 ----
        #pragma unroll
        for (int rb = 0; rb < 2; rb++)
            #pragma unroll
            for (int nn = 0; nn < 3; nn++)
                #pragma unroll
                for (int j = 0; j < 4; j++) c[rb][nn][j] = 0.f;

        #pragma unroll
        for (int kk = 0; kk < 6; kk++) {
            const int kb = kk * 8 + tq;
            uint2 A[2][4];
            #pragma unroll
            for (int rb = 0; rb < 2; rb++) {
                int rr = r0 + rb * 16;
                A[rb][0] = Xp[rr * PX + kb];
                A[rb][1] = Xp[(rr + 8) * PX + kb];
                A[rb][2] = Xp[rr * PX + kb + 4];
                A[rb][3] = Xp[(rr + 8) * PX + kb + 4];
            }
            #pragma unroll
            for (int nn = 0; nn < 3; nn++) {
                uint2 B0 = W2s[kb * PW + ch + nn * 8 + qid];
                uint2 B1 = W2s[(kb + 4) * PW + ch + nn * 8 + qid];
                #pragma unroll
                for (int rb = 0; rb < 2; rb++) {
                    mma16(c[rb][nn], A[rb][0].x, A[rb][1].x, A[rb][2].x, A[rb][3].x, B0.x, B1.x);
                    mma16(c[rb][nn], A[rb][0].x, A[rb][1].x, A[rb][2].x, A[rb][3].x, B0.y, B1.y);
                    mma16(c[rb][nn], A[rb][0].y, A[rb][1].y, A[rb][2].y, A[rb][3].y, B0.x, B1.x);
                }
            }
        }

        #pragma unroll
        for (int rb = 0; rb < 2; rb++) {
            int grow0 = row0 + r0 + rb * 16;
            int grow1 = grow0 + 8;
            #pragma unroll
            for (int nn = 0; nn < 3; nn++) {
                int col = ch + nn * 8 + 2 * tq;
                float2 bb = __ldg(b2v + (col >> 1));
                if (grow0 < nrows) {
                    float2 o = make_float2(c[rb][nn][0] + bb.x, c[rb][nn][1] + bb.y);
                    *reinterpret_cast<float2*>(Y + (size_t)grow0 * D + col) = o;
                }
                if (grow1 < nrows) {
                    float2 o = make_float2(c[rb][nn][2] + bb.x, c[rb][nn][3] + bb.y);
                    *reinterpret_cast<float2*>(Y + (size_t)grow1 * D + col) = o;
                }
            }
        }
        __syncthreads();   // Xp free for next tile
    }
}

// ---------------------------------------------------------------------------
// Launch
// ---------------------------------------------------------------------------
extern "C" void kernel_launch(void* const* d_in, const int* in_sizes, int n_in,
                              void* d_out, int out_size) {
    const float* feat = (const float*)d_in[0];
    const float* W1   = (const float*)d_in[1];
    const float* b1   = (const float*)d_in[2];
    const float* W2   = (const float*)d_in[3];
    const float* b2   = (const float*)d_in[4];
    const int* esrc   = (const int*)d_in[5];
    const int* edst   = (const int*)d_in[6];
    float* out = (float*)d_out;

    int n_edges = in_sizes[5];

    // Prep: counter zero + packed-weight build
    prep_kernel<<<(N_NODES + 255) / 256, 256>>>(W1, W2);

    // Slot table build: 4 edges per thread
    int fthreads = (n_edges + 3) / 4;
    fill_slots<<<(fthreads + 255) / 256, 256>>>(esrc, edst, n_edges);

    // Gather: 4 nodes per warp, emits packed bf16 hi/lo
    int gblocks = (N_NODES + 31) / 32;
    gather_kernel<<<gblocks, 256>>>((const float4*)feat);

    // Tensor-core MLP (3xBF16), M32xN24 warp tiles
    const int smem_bytes = (2 * NK2 * PW + BM * PX) * (int)sizeof(uint2); // 103424
    cudaFuncSetAttribute(mlp_mma,
                         cudaFuncAttributeMaxDynamicSharedMemorySize, smem_bytes);
    mlp_mma<<<MLP_BLOCKS, 256, smem_bytes>>>(b1, b2, out, N_NODES);
}